// round 3
// baseline (speedup 1.0000x reference)
#include <cuda_runtime.h>
#include <cuda_bf16.h>

// Problem constants (fixed by dataset)
#define NV    4096          // N = H*W = 64*64
#define WW    64            // width
#define CAP   128           // per-row bucket capacity (Poisson(20), max ~50)
#define NNZCM 81920         // 20*N
#define MLOC  2048
#define MIU   2048

#define BUILD_BLOCKS  320   // NNZCM / 256  (low block ids -> scheduled first)
#define ZERO_BLOCKS   1184  // zeroing portion (148 SMs * 8)
#define REST_BLOCKS   128   // (MLOC*9 + MIU*5 + NV) / 256 = 32768/256

// Scratch (static device globals — zero-initialized at module load;
// k_mega re-zeroes g_cnt/g_rowsum after consuming them, so every call
// sees the same entry state. No separate reset launch needed.)
__device__ int   g_cnt[NV];
__device__ float g_rowsum[NV];
__device__ int   g_col[NV * CAP];
__device__ float g_val[NV * CAP];

// ---------------------------------------------------------------------------
// kernel1: blocks [0, BUILD_BLOCKS) bucket CM COO entries (critical-path
//          producer — scheduled in wave 1);
//          blocks [BUILD_BLOCKS, +ZERO_BLOCKS) zero d_out (A and b) with
//          16B stores. Disjoint memory -> perfect overlap; the 67 MB HBM
//          write hides the bucket build entirely.
__global__ void k_zero_build(float4* __restrict__ out4,
                             const int* __restrict__ row,
                             const int* __restrict__ col,
                             const float* __restrict__ data,
                             const float* __restrict__ cmw) {
    int blk = blockIdx.x;
    if (blk < BUILD_BLOCKS) {
        int e = blk * blockDim.x + threadIdx.x;
        if (e >= NNZCM) return;
        int r = row[e];
        int c = col[e];
        float v = data[e] * __ldg(&cmw[r]);
        int slot = atomicAdd(&g_cnt[r], 1);
        if (slot < CAP) {
            g_col[r * CAP + slot] = c;
            g_val[r * CAP + slot] = v;
        }
        atomicAdd(&g_rowsum[r], v);
    } else {
        // (NV*NV + NV) floats = 16,781,312 -> 4,195,328 float4 (exact)
        const size_t total4 = ((size_t)NV * NV + NV) / 4;
        const float4 z = make_float4(0.f, 0.f, 0.f, 0.f);
        size_t stride = (size_t)ZERO_BLOCKS * blockDim.x;
        for (size_t i = (size_t)(blk - BUILD_BLOCKS) * blockDim.x + threadIdx.x;
             i < total4; i += stride)
            out4[i] = z;
    }
}

// ---------------------------------------------------------------------------
// kernel2: blocks [0, NV): per-row outer product of Lcm rows (Lcm^T Lcm),
//          then reset that row's bucket state for the next call.
//          blocks [NV, NV+REST_BLOCKS): LOC + IU symmetric-Laplacian
//          scatters and diagonal/b pass, flat-indexed.
//
// Outer product: row k of Lcm as an entry list is
// [(c_e, -v_e) for e in bucket k] + [(k, rowsum_k)]. All-pairs products over
// the raw (duplicate-bearing) list equal the outer product of the accumulated
// dense row by bilinearity — no dedup needed.
__global__ void k_mega(float* __restrict__ A,
                       float* __restrict__ b,
                       const int* __restrict__ LOC_inInd,
                       const float* __restrict__ LOC_flows,   // (9,9,MLOC)
                       const float* __restrict__ locw,
                       const int* __restrict__ IU_inInd,
                       const float* __restrict__ IU_flows,    // (MIU,5)
                       const int* __restrict__ IU_neigh,      // (MIU,5)
                       const float* __restrict__ iuw,
                       const float* __restrict__ kuw,
                       const float* __restrict__ kToUconf,
                       const float* __restrict__ known,
                       const float* __restrict__ kToU,
                       const float* __restrict__ lmbda) {
    int blk = blockIdx.x;
    if (blk < NV) {
        // ---- Lcm^T Lcm outer-product for row k ----
        int k = blk;
        __shared__ int   scol[CAP + 1];
        __shared__ float sval[CAP + 1];
        int n = g_cnt[k];
        if (n > CAP) n = CAP;
        for (int i = threadIdx.x; i < n; i += blockDim.x) {
            scol[i] = g_col[k * CAP + i];
            sval[i] = -g_val[k * CAP + i];
        }
        if (threadIdx.x == 0) {
            scol[n] = k;
            sval[n] = g_rowsum[k];
            // reset bucket state for next call (restores zero-entry invariant)
            g_cnt[k] = 0;
            g_rowsum[k] = 0.0f;
        }
        __syncthreads();
        int m = n + 1;
        int total = m * m;
        for (int p = threadIdx.x; p < total; p += blockDim.x) {
            int i = p / m;
            int j = p - i * m;
            atomicAdd(&A[(size_t)scol[i] * NV + scol[j]], sval[i] * sval[j]);
        }
    } else {
        // ---- flat-indexed LOC / IU / diag ----
        int t = (blk - NV) * blockDim.x + threadIdx.x;
        if (t < MLOC * 9) {
            // LOC: raw entry (r0, c_j, v); fold of symmetrize + Laplacian:
            // A[r0,c]-=v/2; A[c,r0]-=v/2; A[r0,r0]+=v/2; A[c,c]+=v/2
            int m = t & (MLOC - 1);
            int j = t >> 11;                    // MLOC = 2048
            const int offs[9] = { -1 - WW, -1, -1 + WW, -WW, 0, WW, 1 - WW, 1, 1 + WW };
            int base = __ldg(&LOC_inInd[m]);
            int r0 = base + offs[0];
            int c  = base + offs[j];
            float h = 0.5f * __ldg(&LOC_flows[(size_t)j * 9 * MLOC + m]) * __ldg(&locw[base]);
            atomicAdd(&A[(size_t)r0 * NV + c], -h);
            atomicAdd(&A[(size_t)c  * NV + r0], -h);
            atomicAdd(&A[(size_t)r0 * NV + r0],  h);
            atomicAdd(&A[(size_t)c  * NV + c],   h);
        } else if (t < MLOC * 9 + MIU * 5) {
            int u = t - MLOC * 9;
            int m = u / 5;
            int j = u - m * 5;
            int r = __ldg(&IU_inInd[m]);
            int c = __ldg(&IU_neigh[m * 5 + j]);
            float h = 0.5f * __ldg(&IU_flows[m * 5 + j]) * __ldg(&iuw[r]);
            atomicAdd(&A[(size_t)r * NV + c], -h);
            atomicAdd(&A[(size_t)c * NV + r], -h);
            atomicAdd(&A[(size_t)r * NV + r],  h);
            atomicAdd(&A[(size_t)c * NV + c],  h);
        } else if (t < MLOC * 9 + MIU * 5 + NV) {
            int i = t - MLOC * 9 - MIU * 5;
            float d = __ldg(&kuw[i]) * __ldg(&kToUconf[i]) + __ldg(&lmbda[0]) * __ldg(&known[i]);
            atomicAdd(&A[(size_t)i * NV + i], d);
            b[i] = d * __ldg(&kToU[i]);
        }
    }
}

// ---------------------------------------------------------------------------
extern "C" void kernel_launch(void* const* d_in, const int* in_sizes, int n_in,
                              void* d_out, int out_size) {
    const float* CM_weights  = (const float*)d_in[2];
    const float* LOC_weights = (const float*)d_in[3];
    const float* IU_weights  = (const float*)d_in[4];
    const float* KU_weights  = (const float*)d_in[5];
    const float* lmbda       = (const float*)d_in[6];
    const float* kToUconf    = (const float*)d_in[7];
    const float* known       = (const float*)d_in[8];
    const float* kToU        = (const float*)d_in[9];
    const int*   Wcm_row     = (const int*)d_in[10];
    const int*   Wcm_col     = (const int*)d_in[11];
    const float* Wcm_data    = (const float*)d_in[12];
    const int*   LOC_inInd   = (const int*)d_in[13];
    const float* LOC_flows   = (const float*)d_in[14];
    const int*   IU_inInd    = (const int*)d_in[15];
    const float* IU_flows    = (const float*)d_in[16];
    const int*   IU_neighInd = (const int*)d_in[17];

    float* A = (float*)d_out;
    float* b = (float*)d_out + (size_t)NV * NV;

    k_zero_build<<<BUILD_BLOCKS + ZERO_BLOCKS, 256>>>(
        (float4*)d_out, Wcm_row, Wcm_col, Wcm_data, CM_weights);

    k_mega<<<NV + REST_BLOCKS, 256>>>(
        A, b,
        LOC_inInd, LOC_flows, LOC_weights,
        IU_inInd, IU_flows, IU_neighInd, IU_weights,
        KU_weights, kToUconf, known, kToU, lmbda);
}

// round 7
// speedup vs baseline: 1.2066x; 1.2066x over previous
#include <cuda_runtime.h>
#include <cuda_bf16.h>

// Problem constants (fixed by dataset)
#define NV    4096          // N = H*W
#define WW    64            // width
#define CAP   128           // row/col bucket capacity (Binomial mean 20, max ~50)
#define ECAP  512           // per-row LOC/IU contribution bin capacity
#define NNZCM 81920
#define MLOC  2048
#define MIU   2048

// Scratch (static device globals). k_reset zeroes all counters at the start
// of every call, so there is NO cross-call invariant and no cross-block
// coordination anywhere.
__device__ int   g_rcnt[NV];           // row-bucket counts (Lcm rows)
__device__ float g_rowsum[NV];         // Wcm row sums
__device__ int   g_rcol[NV * CAP];     // row-bucket columns
__device__ float g_rval[NV * CAP];     // row-bucket values (v = data*cmw[r])
__device__ int   g_ccnt[NV];           // col-bucket counts (Lcm columns)
__device__ int   g_ck  [NV * CAP];     // col-bucket row indices k
__device__ float g_cv  [NV * CAP];     // col-bucket values
__device__ int   g_ecnt[NV];           // per-row LOC/IU bin counts
__device__ int   g_ecol[NV * ECAP];
__device__ float g_eval[NV * ECAP];

__device__ __forceinline__ void push_e(int r, int c, float v) {
    int s = atomicAdd(&g_ecnt[r], 1);
    if (s < ECAP) { g_ecol[r * ECAP + s] = c; g_eval[r * ECAP + s] = v; }
}

// ---------------------------------------------------------------------------
// Phase 0: zero all per-row counters (16 K ints + 4 K floats).
__global__ void __launch_bounds__(256) k_reset() {
    int i = blockIdx.x * blockDim.x + threadIdx.x;
    if (i < NV) {
        g_rcnt[i] = 0;
        g_ccnt[i] = 0;
        g_ecnt[i] = 0;
        g_rowsum[i] = 0.0f;
    }
}

// ---------------------------------------------------------------------------
// Phase 1: one flat grid builds
//   (a) Lcm row buckets + column buckets + row sums from the CM COO list
//   (b) per-destination-row bins of the LOC and IU symmetric-Laplacian
//       contributions (per raw entry (r,c,v):
//       A[r,c]-=v/2, A[c,r]-=v/2, A[r,r]+=v/2, A[c,c]+=v/2)
__global__ void __launch_bounds__(256)
k_build(const int* __restrict__ Wcm_row,
        const int* __restrict__ Wcm_col,
        const float* __restrict__ Wcm_data,
        const float* __restrict__ cmw,
        const int* __restrict__ LOC_inInd,
        const float* __restrict__ LOC_flows,   // (9,9,MLOC)
        const float* __restrict__ locw,
        const int* __restrict__ IU_inInd,
        const float* __restrict__ IU_flows,    // (MIU,5)
        const int* __restrict__ IU_neigh,      // (MIU,5)
        const float* __restrict__ iuw) {
    int t = blockIdx.x * blockDim.x + threadIdx.x;
    if (t < NNZCM) {
        int r = Wcm_row[t];
        int c = Wcm_col[t];
        float v = Wcm_data[t] * __ldg(&cmw[r]);
        int s = atomicAdd(&g_rcnt[r], 1);
        if (s < CAP) { g_rcol[r * CAP + s] = c; g_rval[r * CAP + s] = v; }
        int s2 = atomicAdd(&g_ccnt[c], 1);
        if (s2 < CAP) { g_ck[c * CAP + s2] = r; g_cv[c * CAP + s2] = v; }
        atomicAdd(&g_rowsum[r], v);
    } else if (t < NNZCM + MLOC * 9) {
        int u = t - NNZCM;
        int m = u & (MLOC - 1);
        int j = u >> 11;                        // MLOC = 2048
        const int offs[9] = { -1 - WW, -1, -1 + WW, -WW, 0, WW, 1 - WW, 1, 1 + WW };
        int base = __ldg(&LOC_inInd[m]);
        int r0 = base + offs[0];
        int c  = base + offs[j];
        float h = 0.5f * __ldg(&LOC_flows[(size_t)j * 9 * MLOC + m]) * __ldg(&locw[base]);
        push_e(r0, c, -h);
        push_e(c, r0, -h);
        push_e(r0, r0, h);
        push_e(c, c, h);
    } else if (t < NNZCM + MLOC * 9 + MIU * 5) {
        int u = t - NNZCM - MLOC * 9;
        int m = u / 5;
        int j = u - m * 5;
        int r = __ldg(&IU_inInd[m]);
        int c = __ldg(&IU_neigh[m * 5 + j]);
        float h = 0.5f * __ldg(&IU_flows[m * 5 + j]) * __ldg(&iuw[r]);
        push_e(r, c, -h);
        push_e(c, r, -h);
        push_e(r, r, h);
        push_e(c, c, h);
    }
}

// ---------------------------------------------------------------------------
// Phase 2: one block per output row r.
//   A[r][:] = sum over T(r) of w * (dense row k of Lcm), where
//   T(r) = { (k, -v_e) : raw entry e with col==r } ∪ { (r, rowsum_r) }   and
//   row_k(Lcm) as an entry list = [(c_e, -v_e)] ∪ [(k, rowsum_k)].
//   Duplicates need no dedup (bilinearity). Accumulate in SMEM with shared
//   atomics, fold in binned LOC/IU + diagonal, stream the row out once.
//   No zero pass over A is needed anywhere.
__global__ void __launch_bounds__(256) k_rows(float* __restrict__ A,
                                              float* __restrict__ b,
                                              const float* __restrict__ kuw,
                                              const float* __restrict__ kToUconf,
                                              const float* __restrict__ known,
                                              const float* __restrict__ kToU,
                                              const float* __restrict__ lmbda) {
    int r = blockIdx.x;
    __shared__ float buf[NV];               // 16 KB row accumulator
    float4* buf4 = (float4*)buf;
    const float4 z = make_float4(0.f, 0.f, 0.f, 0.f);
    for (int i = threadIdx.x; i < NV / 4; i += 256) buf4[i] = z;
    __syncthreads();

    int wid  = threadIdx.x >> 5;
    int lane = threadIdx.x & 31;

    // ---- Lcm^T Lcm contribution: warp per outer entry of T(r) ----
    int tc = min(g_ccnt[r], CAP);
    for (int o = wid; o <= tc; o += 8) {
        int k; float w;
        if (o < tc) { k = g_ck[r * CAP + o]; w = -g_cv[r * CAP + o]; }
        else        { k = r;                 w = g_rowsum[r]; }       // diag of col r
        int nk = min(g_rcnt[k], CAP);
        float rs = g_rowsum[k];
        for (int i = lane; i <= nk; i += 32) {
            int c2; float v2;
            if (i < nk) { c2 = g_rcol[k * CAP + i]; v2 = -g_rval[k * CAP + i]; }
            else        { c2 = k;                   v2 = rs; }        // diag of row k
            atomicAdd(&buf[c2], w * v2);
        }
    }

    // ---- binned LOC/IU contributions for this row ----
    int ne = min(g_ecnt[r], ECAP);
    for (int i = threadIdx.x; i < ne; i += 256)
        atomicAdd(&buf[g_ecol[r * ECAP + i]], g_eval[r * ECAP + i]);

    // ---- diagonal regularization + RHS ----
    if (threadIdx.x == 0) {
        float d = __ldg(&kuw[r]) * __ldg(&kToUconf[r])
                + __ldg(&lmbda[0]) * __ldg(&known[r]);
        atomicAdd(&buf[r], d);
        b[r] = d * __ldg(&kToU[r]);
    }
    __syncthreads();

    // ---- stream the finished row to GMEM (coalesced 16B stores) ----
    float4* dst = (float4*)(A + (size_t)r * NV);
    for (int i = threadIdx.x; i < NV / 4; i += 256) dst[i] = buf4[i];
}

// ---------------------------------------------------------------------------
extern "C" void kernel_launch(void* const* d_in, const int* in_sizes, int n_in,
                              void* d_out, int out_size) {
    const float* CM_weights  = (const float*)d_in[2];
    const float* LOC_weights = (const float*)d_in[3];
    const float* IU_weights  = (const float*)d_in[4];
    const float* KU_weights  = (const float*)d_in[5];
    const float* lmbda       = (const float*)d_in[6];
    const float* kToUconf    = (const float*)d_in[7];
    const float* known       = (const float*)d_in[8];
    const float* kToU        = (const float*)d_in[9];
    const int*   Wcm_row     = (const int*)d_in[10];
    const int*   Wcm_col     = (const int*)d_in[11];
    const float* Wcm_data    = (const float*)d_in[12];
    const int*   LOC_inInd   = (const int*)d_in[13];
    const float* LOC_flows   = (const float*)d_in[14];
    const int*   IU_inInd    = (const int*)d_in[15];
    const float* IU_flows    = (const float*)d_in[16];
    const int*   IU_neighInd = (const int*)d_in[17];

    float* A = (float*)d_out;
    float* b = (float*)d_out + (size_t)NV * NV;

    k_reset<<<(NV + 255) / 256, 256>>>();

    // 81920 + 18432 + 10240 = 110592 = 432 * 256
    k_build<<<432, 256>>>(Wcm_row, Wcm_col, Wcm_data, CM_weights,
                          LOC_inInd, LOC_flows, LOC_weights,
                          IU_inInd, IU_flows, IU_neighInd, IU_weights);

    k_rows<<<NV, 256>>>(A, b, KU_weights, kToUconf, known, kToU, lmbda);
}